// round 5
// baseline (speedup 1.0000x reference)
#include <cuda_runtime.h>

#define N_NODES 50000
#define N_EDGES 800000
#define F_IN 128
#define HID 160
#define OUT_C 128
#define NGR 64
#define OUT_DIM 10
#define FP 16            // padded channel count: 10 logit-proj + 1 ones + 5 pad
#define SCAN_B 1024
#define SCAN_NB 49       // ceil(50000/1024)

// ---------------- static scratch (no allocations allowed) ----------------
__device__ int    d_indeg[N_NODES];
__device__ int    d_ptr[N_NODES + 1];
__device__ int    d_cursor[N_NODES];
__device__ float  d_dinv[N_NODES];
__device__ int    d_csrc[N_EDGES];
__device__ float  d_cnorm[N_EDGES];
__device__ float4 d_H0[N_NODES * 4];     // 16 floats per node
__device__ float4 d_H1[N_NODES * 4];
__device__ float  d_c5[N_NODES];
__device__ float  d_c10[N_NODES];
__device__ float  d_P3[HID * OUT_DIM];   // W3 @ fc_w            (160x10)
__device__ float  d_P2[HID * OUT_DIM];   // W2 @ P3              (160x10)
__device__ float  d_R [F_IN * OUT_DIM];  // W1 @ P2              (128x10)
__device__ float  d_g1[OUT_DIM];         // b1 @ P2
__device__ float  d_g2[OUT_DIM];         // b2 @ P3
__device__ float  d_g3[OUT_DIM];         // b3 @ fc_w
__device__ float  d_pooled[NGR * OUT_DIM];
__device__ int    d_counts[NGR];
__device__ int    d_bsum[64];

// ---------------- preprocessing ----------------
__global__ void k_zero_deg() {
    int i = blockIdx.x * blockDim.x + threadIdx.x;
    if (i < N_NODES) d_indeg[i] = 0;
}

__global__ void k_deg(const int* __restrict__ ei) {
    int e = blockIdx.x * blockDim.x + threadIdx.x;
    if (e < N_EDGES) atomicAdd(&d_indeg[ei[N_EDGES + e]], 1);
}

__global__ void k_dinv() {
    int i = blockIdx.x * blockDim.x + threadIdx.x;
    if (i < N_NODES) d_dinv[i] = rsqrtf((float)(d_indeg[i] + 1));
}

// exclusive scan of indeg -> ptr  (3 phases)
__global__ void k_scan1() {
    __shared__ int sm[SCAN_B];
    int i = blockIdx.x * SCAN_B + threadIdx.x;
    int v = (i < N_NODES) ? d_indeg[i] : 0;
    sm[threadIdx.x] = v;
    __syncthreads();
    for (int off = 1; off < SCAN_B; off <<= 1) {
        int t = (threadIdx.x >= (unsigned)off) ? sm[threadIdx.x - off] : 0;
        __syncthreads();
        sm[threadIdx.x] += t;
        __syncthreads();
    }
    if (i < N_NODES) d_ptr[i] = sm[threadIdx.x] - v;   // exclusive
    if (threadIdx.x == SCAN_B - 1) d_bsum[blockIdx.x] = sm[SCAN_B - 1];
}

__global__ void k_scan2() {
    if (threadIdx.x == 0 && blockIdx.x == 0) {
        int run = 0;
        for (int b = 0; b < SCAN_NB; b++) { int t = d_bsum[b]; d_bsum[b] = run; run += t; }
    }
}

__global__ void k_scan3() {
    int i = blockIdx.x * blockDim.x + threadIdx.x;
    if (i < N_NODES) {
        int p = d_ptr[i] + d_bsum[i >> 10];
        d_ptr[i] = p;
        d_cursor[i] = p;
    }
    if (i == 0) d_ptr[N_NODES] = N_EDGES;
}

__global__ void k_scatter(const int* __restrict__ ei) {
    int e = blockIdx.x * blockDim.x + threadIdx.x;
    if (e >= N_EDGES) return;
    int s = ei[e];
    int d = ei[N_EDGES + e];
    int p = atomicAdd(&d_cursor[d], 1);
    d_csrc[p] = s;
    d_cnorm[p] = d_dinv[s] * d_dinv[d];
}

// ---------------- tiny parameter GEMM chain (right-to-left) ----------------
// P3 = W3(160x128) @ fc_w(128x10);  g3 = b3(128) @ fc_w
__global__ void k_par1(const float* __restrict__ W3, const float* __restrict__ fc_w,
                       const float* __restrict__ b3) {
    int t = blockIdx.x * blockDim.x + threadIdx.x;
    if (t < HID * OUT_DIM) {
        int i = t / OUT_DIM, c = t % OUT_DIM;
        float a = 0.f;
        for (int k = 0; k < OUT_C; k++) a += W3[i * OUT_C + k] * fc_w[k * OUT_DIM + c];
        d_P3[t] = a;
    } else if (t < HID * OUT_DIM + OUT_DIM) {
        int c = t - HID * OUT_DIM;
        float a = 0.f;
        for (int k = 0; k < OUT_C; k++) a += b3[k] * fc_w[k * OUT_DIM + c];
        d_g3[c] = a;
    }
}
// P2 = W2(160x160) @ P3;  g2 = b2(160) @ P3
__global__ void k_par2(const float* __restrict__ W2, const float* __restrict__ b2) {
    int t = blockIdx.x * blockDim.x + threadIdx.x;
    if (t < HID * OUT_DIM) {
        int i = t / OUT_DIM, c = t % OUT_DIM;
        float a = 0.f;
        for (int k = 0; k < HID; k++) a += W2[i * HID + k] * d_P3[k * OUT_DIM + c];
        d_P2[t] = a;
    } else if (t < HID * OUT_DIM + OUT_DIM) {
        int c = t - HID * OUT_DIM;
        float a = 0.f;
        for (int k = 0; k < HID; k++) a += b2[k] * d_P3[k * OUT_DIM + c];
        d_g2[c] = a;
    }
}
// R = W1(128x160) @ P2;  g1 = b1(160) @ P2
__global__ void k_par3(const float* __restrict__ W1, const float* __restrict__ b1) {
    int t = blockIdx.x * blockDim.x + threadIdx.x;
    if (t < F_IN * OUT_DIM) {
        int i = t / OUT_DIM, c = t % OUT_DIM;
        float a = 0.f;
        for (int k = 0; k < HID; k++) a += W1[i * HID + k] * d_P2[k * OUT_DIM + c];
        d_R[t] = a;
    } else if (t < F_IN * OUT_DIM + OUT_DIM) {
        int c = t - F_IN * OUT_DIM;
        float a = 0.f;
        for (int k = 0; k < HID; k++) a += b1[k] * d_P2[k * OUT_DIM + c];
        d_g1[c] = a;
    }
}

// ---------------- initial projection: H0[:, 0:10] = X @ R, ch10 = ones ----------------
__global__ void k_init(const float* __restrict__ x) {
    int t = blockIdx.x * blockDim.x + threadIdx.x;
    if (t >= N_NODES * FP) return;
    int n = t >> 4, c = t & 15;
    float v;
    if (c < OUT_DIM) {
        const float* xr = x + n * F_IN;
        float a = 0.f;
        #pragma unroll 8
        for (int k = 0; k < F_IN; k++) a += xr[k] * d_R[k * OUT_DIM + c];
        v = a;
    } else {
        v = (c == 10) ? 1.0f : 0.0f;
    }
    ((float*)d_H0)[t] = v;
}

// ---------------- propagation: out[d] = dinv[d]^2 h[d] + sum_e norm_e h[src_e] ----------------
// quad (4 threads) per dst node; each thread owns one float4 of the 16-float row
__global__ void k_prop(int dir) {
    const float4* __restrict__ h  = dir ? d_H1 : d_H0;
    float4* __restrict__ out      = dir ? d_H0 : d_H1;
    int t = blockIdx.x * blockDim.x + threadIdx.x;
    int node = t >> 2;
    if (node >= N_NODES) return;
    int q = t & 3;
    int e = d_ptr[node], end = d_ptr[node + 1];

    float ax = 0.f, ay = 0.f, az = 0.f, aw = 0.f;
    float bx = 0.f, by = 0.f, bz = 0.f, bw = 0.f;
    for (; e + 1 < end; e += 2) {
        int   s0 = d_csrc[e],  s1 = d_csrc[e + 1];
        float w0 = d_cnorm[e], w1 = d_cnorm[e + 1];
        float4 v0 = h[s0 * 4 + q];
        float4 v1 = h[s1 * 4 + q];
        ax += w0 * v0.x; ay += w0 * v0.y; az += w0 * v0.z; aw += w0 * v0.w;
        bx += w1 * v1.x; by += w1 * v1.y; bz += w1 * v1.z; bw += w1 * v1.w;
    }
    if (e < end) {
        int s0 = d_csrc[e]; float w0 = d_cnorm[e];
        float4 v0 = h[s0 * 4 + q];
        ax += w0 * v0.x; ay += w0 * v0.y; az += w0 * v0.z; aw += w0 * v0.w;
    }
    float dn = d_dinv[node];
    float sw = dn * dn;
    float4 v = h[node * 4 + q];
    ax += sw * v.x + bx;
    ay += sw * v.y + by;
    az += sw * v.z + bz;
    aw += sw * v.w + bw;
    out[node * 4 + q] = make_float4(ax, ay, az, aw);
}

// snapshot ones-channel (channel 10) into c5 / c10
__global__ void k_snap(int fromH1, int toC10) {
    int n = blockIdx.x * blockDim.x + threadIdx.x;
    if (n >= N_NODES) return;
    const float* src = fromH1 ? (const float*)d_H1 : (const float*)d_H0;
    float* dst = toC10 ? d_c10 : d_c5;
    dst[n] = src[n * FP + 10];
}

// ---------------- pooling ----------------
__global__ void k_zeropool() {
    int i = blockIdx.x * blockDim.x + threadIdx.x;
    if (i < NGR * OUT_DIM) d_pooled[i] = 0.f;
    if (i < NGR) d_counts[i] = 0;
}

__global__ void k_pool(const int* __restrict__ batch) {
    __shared__ float sp[NGR * OUT_DIM];
    __shared__ int   sc[NGR];
    int tid = threadIdx.x;
    for (int i = tid; i < NGR * OUT_DIM; i += blockDim.x) sp[i] = 0.f;
    if (tid < NGR) sc[tid] = 0;
    __syncthreads();

    int n = blockIdx.x * blockDim.x + tid;
    if (n < N_NODES) {
        int b = batch[n];
        atomicAdd(&sc[b], 1);
        float a10 = d_c10[n], a5 = d_c5[n];
        const float* hr = ((const float*)d_H1) + n * FP;   // final state after hop 15
        #pragma unroll
        for (int c = 0; c < OUT_DIM; c++) {
            float z = hr[c] + a10 * d_g1[c] + a5 * d_g2[c] + d_g3[c];
            atomicAdd(&sp[b * OUT_DIM + c], z);
        }
    }
    __syncthreads();
    for (int i = tid; i < NGR * OUT_DIM; i += blockDim.x)
        if (sp[i] != 0.f) atomicAdd(&d_pooled[i], sp[i]);
    if (tid < NGR && sc[tid]) atomicAdd(&d_counts[tid], sc[tid]);
}

// ---------------- final: mean, +fc_b, log_softmax ----------------
__global__ void k_final(const float* __restrict__ fc_b, float* __restrict__ out) {
    int g = threadIdx.x;
    if (g >= NGR) return;
    float cnt = (float)d_counts[g];
    if (cnt < 1.f) cnt = 1.f;
    float l[OUT_DIM];
    float m = -1e30f;
    #pragma unroll
    for (int c = 0; c < OUT_DIM; c++) {
        l[c] = d_pooled[g * OUT_DIM + c] / cnt + fc_b[c];
        m = fmaxf(m, l[c]);
    }
    float s = 0.f;
    #pragma unroll
    for (int c = 0; c < OUT_DIM; c++) s += expf(l[c] - m);
    float lse = m + logf(s);
    #pragma unroll
    for (int c = 0; c < OUT_DIM; c++) out[g * OUT_DIM + c] = l[c] - lse;
}

// ---------------- launch ----------------
extern "C" void kernel_launch(void* const* d_in, const int* in_sizes, int n_in,
                              void* d_out, int out_size) {
    (void)in_sizes; (void)n_in; (void)out_size;
    const float* x     = (const float*)d_in[0];
    const int*   ei    = (const int*)d_in[1];     // JAX default x64-disabled: int32
    const int*   batch = (const int*)d_in[2];     // int32
    const float* W1    = (const float*)d_in[3];
    const float* b1    = (const float*)d_in[4];
    const float* W2    = (const float*)d_in[5];
    const float* b2    = (const float*)d_in[6];
    const float* W3    = (const float*)d_in[7];
    const float* b3    = (const float*)d_in[8];
    const float* fc_w  = (const float*)d_in[9];
    const float* fc_b  = (const float*)d_in[10];
    float* out = (float*)d_out;

    const int TB = 256;
    const int gN  = (N_NODES + TB - 1) / TB;            // 196
    const int gE  = (N_EDGES + TB - 1) / TB;            // 3125
    const int gNF = (N_NODES * FP + TB - 1) / TB;       // 3125
    const int gP  = (N_NODES * 4 + TB - 1) / TB;        // 782
    const int gPar = (HID * OUT_DIM + OUT_DIM + TB - 1) / TB;

    // degrees / norms
    k_zero_deg<<<gN, TB>>>();
    k_deg<<<gE, TB>>>(ei);
    k_dinv<<<gN, TB>>>();
    // CSR by dst
    k_scan1<<<SCAN_NB, SCAN_B>>>();
    k_scan2<<<1, 32>>>();
    k_scan3<<<gN, TB>>>();
    k_scatter<<<gE, TB>>>(ei);
    // parameter chain
    k_par1<<<gPar, TB>>>(W3, fc_w, b3);
    k_par2<<<gPar, TB>>>(W2, b2);
    k_par3<<<gPar, TB>>>(W1, b1);
    // initial projection
    k_init<<<gNF, TB>>>(x);
    // 15 hops, ping-pong H0 <-> H1
    int dir = 0;
    for (int h = 1; h <= 15; h++) {
        k_prop<<<gP, TB>>>(dir);
        dir ^= 1;
        if (h == 5)  k_snap<<<gN, TB>>>(/*fromH1=*/1, /*toC10=*/0);  // hop5 result in H1
        if (h == 10) k_snap<<<gN, TB>>>(/*fromH1=*/0, /*toC10=*/1);  // hop10 result in H0
    }
    // pool + final
    k_zeropool<<<3, TB>>>();
    k_pool<<<gN, TB>>>(batch);
    k_final<<<1, NGR>>>(fc_b, out);
}